// round 1
// baseline (speedup 1.0000x reference)
#include <cuda_runtime.h>
#include <math.h>

#define BTOT 512
#define NMEM 30
#define HW 1024
#define NGTH_ 15
#define TPB 288

// Scratch: 14-channel stats tensor (B, 14, 32, 32)
__device__ float g_inp[(size_t)BTOT * 14 * HW];

// ---------------------------------------------------------------------------
// Kernel 1: per-image statistics -> g_inp (14 channels)
// ---------------------------------------------------------------------------
__global__ __launch_bounds__(256) void stats_kernel(
    const float* __restrict__ ts,
    const float* __restrict__ ptm,
    const float* __restrict__ pmt,
    const float* __restrict__ piou,
    const void* __restrict__ mask_raw)
{
    const int b = blockIdx.x;
    const int tid = threadIdx.x;
    const int lane = tid & 31;
    const int wid = tid >> 5;

    __shared__ float mf[NMEM], gw[NMEM], ow[NMEM];
    __shared__ float pmax[NMEM];
    __shared__ float warpmax[8];
    __shared__ float sc[16]; // 0:max_ts 1..6:m_mm,s_mm,m_gm,s_gm,m_om,s_om 7:cnt_a 8:cnt_g 9:cnt_o

    // mask dtype detection: first 30-elem row starts with >=4 True values
    unsigned int w0 = *(const unsigned int*)mask_raw;
    int mode = (w0 == 1u) ? 1 : ((w0 == 0x3F800000u) ? 2 : 0);

    if (tid == 0) {
        float run = 0.f, ca = 0.f, cg = 0.f, co = 0.f;
        for (int m = 0; m < NMEM; ++m) {
            int idx = b * NMEM + m;
            float f;
            if (mode == 1)      f = (((const int*)mask_raw)[idx] != 0) ? 1.f : 0.f;
            else if (mode == 2) f = (((const float*)mask_raw)[idx] != 0.f) ? 1.f : 0.f;
            else                f = (((const unsigned char*)mask_raw)[idx] != 0) ? 1.f : 0.f;
            run += f;
            float rank = run - 1.f;
            float g = (rank < (float)NGTH_) ? f : 0.f;
            float o = f - g;
            mf[m] = f; gw[m] = g; ow[m] = o;
            ca += f; cg += g; co += o;
        }
        sc[7] = ca; sc[8] = cg; sc[9] = co;
    }

    // target_scores max
    float tmax = -INFINITY;
    const float* tsb = ts + (size_t)b * HW;
    for (int p = tid; p < HW; p += 256) tmax = fmaxf(tmax, tsb[p]);
    #pragma unroll
    for (int off = 16; off > 0; off >>= 1)
        tmax = fmaxf(tmax, __shfl_xor_sync(0xffffffffu, tmax, off));
    if (lane == 0) warpmax[wid] = tmax;

    // per-memory spatial max of ptm (warp w handles mems w, w+8, ...)
    const float* ptmb = ptm + (size_t)b * NMEM * HW;
    for (int m = wid; m < NMEM; m += 8) {
        float mx = -INFINITY;
        const float* pr = ptmb + (size_t)m * HW;
        for (int p = lane; p < HW; p += 32) mx = fmaxf(mx, pr[p]);
        #pragma unroll
        for (int off = 16; off > 0; off >>= 1)
            mx = fmaxf(mx, __shfl_xor_sync(0xffffffffu, mx, off));
        if (lane == 0) pmax[m] = mx;
    }
    __syncthreads();

    if (wid == 0) {
        float v = (lane < 8) ? warpmax[lane] : -INFINITY;
        #pragma unroll
        for (int off = 4; off > 0; off >>= 1)
            v = fmaxf(v, __shfl_xor_sync(0xffffffffu, v, off));
        if (lane == 0) sc[0] = v;
    }
    if (wid == 1) {
        float v  = (lane < NMEM) ? pmax[lane] : 0.f;
        float fa = (lane < NMEM) ? mf[lane] : 0.f;
        float fg = (lane < NMEM) ? gw[lane] : 0.f;
        float fo = (lane < NMEM) ? ow[lane] : 0.f;
        float sa = v * fa, ssa = v * v * fa;
        float sg = v * fg, ssg = v * v * fg;
        float so = v * fo, sso = v * v * fo;
        #pragma unroll
        for (int off = 16; off > 0; off >>= 1) {
            sa  += __shfl_xor_sync(0xffffffffu, sa, off);
            ssa += __shfl_xor_sync(0xffffffffu, ssa, off);
            sg  += __shfl_xor_sync(0xffffffffu, sg, off);
            ssg += __shfl_xor_sync(0xffffffffu, ssg, off);
            so  += __shfl_xor_sync(0xffffffffu, so, off);
            sso += __shfl_xor_sync(0xffffffffu, sso, off);
        }
        if (lane == 0) {
            float ca = sc[7], cg = sc[8], co = sc[9];
            float mA = sa / ca; sc[1] = mA; sc[2] = sqrtf(fmaxf(ssa / ca - mA * mA, 0.f));
            float mG = sg / cg; sc[3] = mG; sc[4] = sqrtf(fmaxf(ssg / cg - mG * mG, 0.f));
            float mO = so / co; sc[5] = mO; sc[6] = sqrtf(fmaxf(sso / co - mO * mO, 0.f));
        }
    }
    __syncthreads();

    const float pv = piou[b];
    float* ob = g_inp + (size_t)b * 14 * HW;
    const float* pmtb = pmt + (size_t)b * NMEM * HW;
    const float c0 = sc[0];
    const float ca = sc[7], co = sc[9];
    const float s8 = sc[1], s9 = sc[2], s10 = sc[3], s11 = sc[4], s12 = sc[5], s13 = sc[6];

    for (int p = tid; p < HW; p += 256) {
        float sa = 0, ssa = 0, sg = 0, ssg = 0, so = 0, sso = 0;
        #pragma unroll 5
        for (int m = 0; m < NMEM; ++m) {
            float v = pmtb[(size_t)m * HW + p];
            float fa = mf[m], fo = ow[m];
            sa += v * fa; ssa += v * v * fa;
            if (m < NGTH_) { sg += v; ssg += v * v; }
            so += v * fo; sso += v * v * fo;
        }
        float mA = sa / ca, sA = sqrtf(fmaxf(ssa / ca - mA * mA, 0.f));
        float mG = sg * (1.f / NGTH_), sG = sqrtf(fmaxf(ssg * (1.f / NGTH_) - mG * mG, 0.f));
        float mO = so / co, sO = sqrtf(fmaxf(sso / co - mO * mO, 0.f));
        ob[0 * HW + p] = c0;
        ob[1 * HW + p] = pv;
        ob[2 * HW + p] = mA;
        ob[3 * HW + p] = sA;
        ob[4 * HW + p] = mG;
        ob[5 * HW + p] = sG;
        ob[6 * HW + p] = mO;
        ob[7 * HW + p] = sO;
        ob[8 * HW + p] = s8;
        ob[9 * HW + p] = s9;
        ob[10 * HW + p] = s10;
        ob[11 * HW + p] = s11;
        ob[12 * HW + p] = s12;
        ob[13 * HW + p] = s13;
    }
}

// ---------------------------------------------------------------------------
// Fused CNN kernel: one CTA per image, all intermediates in SMEM
// smem layout (floats):
//   A   [0,      14336)  conv1 input (14x32x32) / x2 (64x13x13)
//   B   [14336,  28736)  x1 pooled (64x15x15)   / x3 (64x11x11)
//   W   [28736,  53312)  weights, padded to 12 floats per (oc,ic) tap-set
//   E   [53312,  53440)  folded BN scale[64] + bias[64]
//   RED [53440,  53456)  reduction scratch
// ---------------------------------------------------------------------------
#define OA 0
#define OB 14336
#define OWT 28736
#define OE 53312
#define ORED 53440
#define SMEM_FLOATS 53456
#define SMEM_BYTES (SMEM_FLOATS * 4)

// generic 3x3 valid conv, 64->64, bn+relu. OWD = output width, POSW = cols per item.
template<int OWD, int POSW>
__device__ __forceinline__ void conv64_stage(
    float* sm, int inOff, int outOff,
    const float* __restrict__ wg,
    const float* __restrict__ cbv, const float* __restrict__ gv,
    const float* __restrict__ bbv, const float* __restrict__ mv,
    const float* __restrict__ vv)
{
    constexpr int IW = OWD + 2;
    constexpr int ISZ = IW * IW;
    constexpr int OSZ = OWD * OWD;
    constexpr int CT = (OWD + POSW - 1) / POSW;
    const int tid = threadIdx.x;

    __syncthreads();  // stage boundary: prev outputs committed, prev E/W reads done
    if (tid < 64) {
        float s = gv[tid] * rsqrtf(vv[tid] + 1e-5f);
        sm[OE + tid] = s;
        sm[OE + 64 + tid] = s * (cbv[tid] - mv[tid]) + bbv[tid];
    }

    for (int chunk = 0; chunk < 2; ++chunk) {
        if (chunk) __syncthreads();
        // load 32-oc weight chunk, padded layout [o][ic][12]
        const float* ws = wg + chunk * (32 * 64 * 9);
        for (int i = tid; i < 32 * 64 * 9; i += TPB) {
            int o = i / 576; int rr = i - o * 576;
            int ic = rr / 9; int k = rr - ic * 9;
            sm[OWT + (o * 64 + ic) * 12 + k] = ws[i];
        }
        __syncthreads();

        for (int it = tid; it < 4 * OWD * CT; it += TPB) {
            int ct = it % CT;
            int row = (it / CT) % OWD;
            int sub = it / (CT * OWD);
            int oc0l = sub * 8;
            int oc0 = chunk * 32 + oc0l;
            int x0 = ct * POSW;

            float acc[8][POSW];
            #pragma unroll
            for (int o = 0; o < 8; ++o)
                #pragma unroll
                for (int p = 0; p < POSW; ++p) acc[o][p] = 0.f;

            for (int ic = 0; ic < 64; ++ic) {
                float r[3][POSW + 2];
                const float* ib = &sm[inOff + ic * ISZ + row * IW + x0];
                #pragma unroll
                for (int rr = 0; rr < 3; ++rr)
                    #pragma unroll
                    for (int cc = 0; cc < POSW + 2; ++cc)
                        r[rr][cc] = ib[rr * IW + cc];

                #pragma unroll
                for (int o = 0; o < 8; ++o) {
                    const float4* wq = (const float4*)&sm[OWT + ((oc0l + o) * 64 + ic) * 12];
                    float4 qa = wq[0], qb = wq[1], qc = wq[2];
                    float wv[9] = {qa.x, qa.y, qa.z, qa.w, qb.x, qb.y, qb.z, qb.w, qc.x};
                    #pragma unroll
                    for (int ky = 0; ky < 3; ++ky)
                        #pragma unroll
                        for (int kx = 0; kx < 3; ++kx) {
                            float wvv = wv[ky * 3 + kx];
                            #pragma unroll
                            for (int p = 0; p < POSW; ++p)
                                acc[o][p] += wvv * r[ky][p + kx];
                        }
                }
            }
            #pragma unroll
            for (int o = 0; o < 8; ++o) {
                float s = sm[OE + oc0 + o], bia = sm[OE + 64 + oc0 + o];
                #pragma unroll
                for (int p = 0; p < POSW; ++p) {
                    int x = x0 + p;
                    if (x < OWD)
                        sm[outOff + (oc0 + o) * OSZ + row * OWD + x] =
                            fmaxf(s * acc[o][p] + bia, 0.f);
                }
            }
        }
    }
}

__global__ __launch_bounds__(TPB, 1) void cnn_kernel(
    const float* __restrict__ w1, const float* __restrict__ cb1,
    const float* __restrict__ g1, const float* __restrict__ bb1,
    const float* __restrict__ m1, const float* __restrict__ v1,
    const float* __restrict__ w2, const float* __restrict__ cb2,
    const float* __restrict__ g2, const float* __restrict__ bb2,
    const float* __restrict__ m2, const float* __restrict__ v2,
    const float* __restrict__ w3, const float* __restrict__ cb3,
    const float* __restrict__ g3, const float* __restrict__ bb3,
    const float* __restrict__ m3, const float* __restrict__ v3,
    const float* __restrict__ w4, const float* __restrict__ cb4,
    float* __restrict__ out)
{
    extern __shared__ float sm[];
    const int b = blockIdx.x;
    const int tid = threadIdx.x;

    // ---------------- stage 1 prologue: input, w1 (padded), eff1 ----------------
    {
        const float* src = g_inp + (size_t)b * 14 * HW;
        for (int i = tid; i < 14 * HW; i += TPB) sm[OA + i] = src[i];
        for (int i = tid; i < 64 * 14 * 9; i += TPB) {
            int oc = i / 126; int rr = i - oc * 126;
            int ic = rr / 9; int k = rr - ic * 9;
            sm[OWT + (oc * 14 + ic) * 12 + k] = w1[i];
        }
        if (tid < 64) {
            float s = g1[tid] * rsqrtf(v1[tid] + 1e-5f);
            sm[OE + tid] = s;
            sm[OE + 64 + tid] = s * (cb1[tid] - m1[tid]) + bb1[tid];
        }
    }
    __syncthreads();

    // ---------------- stage 1: conv1 (14->64, 32x32 -> 30x30) + bn + relu + pool -> B (64x15x15)
    // item: chunk(16 of 4oc) x row(15) x ct(8 of 2 pooled cols)
    for (int it = tid; it < 16 * 15 * 8; it += TPB) {
        int ct = it & 7;
        int row = (it >> 3) % 15;
        int chunk = (it >> 3) / 15;
        int oc0 = chunk * 4;
        int px0 = ct * 2;

        float acc[4][8];
        #pragma unroll
        for (int o = 0; o < 4; ++o)
            #pragma unroll
            for (int q = 0; q < 8; ++q) acc[o][q] = 0.f;

        for (int ic = 0; ic < 14; ++ic) {
            float r[4][6];
            const float* ib = &sm[OA + ic * HW + (2 * row) * 32 + 2 * px0];
            #pragma unroll
            for (int rr = 0; rr < 4; ++rr)
                #pragma unroll
                for (int cc = 0; cc < 6; ++cc)
                    r[rr][cc] = ib[rr * 32 + cc];

            #pragma unroll
            for (int o = 0; o < 4; ++o) {
                const float4* wq = (const float4*)&sm[OWT + ((oc0 + o) * 14 + ic) * 12];
                float4 qa = wq[0], qb = wq[1], qc = wq[2];
                float wv[9] = {qa.x, qa.y, qa.z, qa.w, qb.x, qb.y, qb.z, qb.w, qc.x};
                #pragma unroll
                for (int ky = 0; ky < 3; ++ky)
                    #pragma unroll
                    for (int kx = 0; kx < 3; ++kx) {
                        float wvv = wv[ky * 3 + kx];
                        #pragma unroll
                        for (int j = 0; j < 2; ++j)
                            #pragma unroll
                            for (int dy = 0; dy < 2; ++dy)
                                #pragma unroll
                                for (int dx = 0; dx < 2; ++dx)
                                    acc[o][j * 4 + dy * 2 + dx] += wvv * r[dy + ky][2 * j + dx + kx];
                    }
            }
        }
        #pragma unroll
        for (int o = 0; o < 4; ++o) {
            float s = sm[OE + oc0 + o], bia = sm[OE + 64 + oc0 + o];
            #pragma unroll
            for (int j = 0; j < 2; ++j) {
                int px = px0 + j;
                if (px < 15) {
                    float v0 = fmaxf(s * acc[o][j * 4 + 0] + bia, 0.f);
                    float v1_ = fmaxf(s * acc[o][j * 4 + 1] + bia, 0.f);
                    float v2_ = fmaxf(s * acc[o][j * 4 + 2] + bia, 0.f);
                    float v3_ = fmaxf(s * acc[o][j * 4 + 3] + bia, 0.f);
                    sm[OB + (oc0 + o) * 225 + row * 15 + px] =
                        fmaxf(fmaxf(v0, v1_), fmaxf(v2_, v3_));
                }
            }
        }
    }

    // ---------------- stage 2: conv2 (64->64, 15x15 -> 13x13), B -> A ----------------
    conv64_stage<13, 4>(sm, OB, OA, w2, cb2, g2, bb2, m2, v2);

    // ---------------- stage 3: conv3 (64->64, 13x13 -> 11x11), A -> B ----------------
    conv64_stage<11, 2>(sm, OA, OB, w3, cb3, g3, bb3, m3, v3);

    // ---------------- stage 4: conv4 (64->1, 11x11 -> 9x9) + global max ----------------
    __syncthreads();
    for (int i = tid; i < 576; i += TPB) sm[OWT + i] = w4[i];
    __syncthreads();

    float lmax = -INFINITY;
    for (int p = tid; p < 81; p += TPB) {
        int y = p / 9, x = p - (p / 9) * 9;
        float a = 0.f;
        for (int ic = 0; ic < 64; ++ic) {
            const float* ib = &sm[OB + ic * 121 + y * 11 + x];
            const float* wb = &sm[OWT + ic * 9];
            #pragma unroll
            for (int ky = 0; ky < 3; ++ky)
                #pragma unroll
                for (int kx = 0; kx < 3; ++kx)
                    a += ib[ky * 11 + kx] * wb[ky * 3 + kx];
        }
        lmax = fmaxf(lmax, a);
    }
    #pragma unroll
    for (int off = 16; off > 0; off >>= 1)
        lmax = fmaxf(lmax, __shfl_xor_sync(0xffffffffu, lmax, off));
    if ((tid & 31) == 0) sm[ORED + (tid >> 5)] = lmax;
    __syncthreads();
    if (tid < 32) {
        float v = (tid < TPB / 32) ? sm[ORED + tid] : -INFINITY;
        #pragma unroll
        for (int off = 16; off > 0; off >>= 1)
            v = fmaxf(v, __shfl_xor_sync(0xffffffffu, v, off));
        if (tid == 0) out[b] = v + cb4[0];
    }
}

// ---------------------------------------------------------------------------
extern "C" void kernel_launch(void* const* d_in, const int* in_sizes, int n_in,
                              void* d_out, int out_size)
{
    cudaFuncSetAttribute(cnn_kernel, cudaFuncAttributeMaxDynamicSharedMemorySize, SMEM_BYTES);

    stats_kernel<<<BTOT, 256>>>(
        (const float*)d_in[0],   // target_scores
        (const float*)d_in[1],   // ptm
        (const float*)d_in[2],   // pmt
        (const float*)d_in[3],   // predicted_iou
        d_in[4]);                // mem_mask (dtype auto-detected)

    cnn_kernel<<<BTOT, TPB, SMEM_BYTES>>>(
        (const float*)d_in[5],  (const float*)d_in[6],
        (const float*)d_in[7],  (const float*)d_in[8],
        (const float*)d_in[9],  (const float*)d_in[10],
        (const float*)d_in[11], (const float*)d_in[12],
        (const float*)d_in[13], (const float*)d_in[14],
        (const float*)d_in[15], (const float*)d_in[16],
        (const float*)d_in[17], (const float*)d_in[18],
        (const float*)d_in[19], (const float*)d_in[20],
        (const float*)d_in[21], (const float*)d_in[22],
        (const float*)d_in[23], (const float*)d_in[24],
        (float*)d_out);
}

// round 2
// speedup vs baseline: 1.0685x; 1.0685x over previous
#include <cuda_runtime.h>
#include <math.h>

#define BTOT 512
#define NMEM 30
#define HW 1024
#define NGTH_ 15
#define TPB 512

typedef unsigned long long u64;

__device__ __forceinline__ u64 dup2f(float v) {
    u64 r; asm("mov.b64 %0, {%1, %1};" : "=l"(r) : "f"(v)); return r;
}
__device__ __forceinline__ void fma2(u64& d, u64 a, u64 b) {
    asm("fma.rn.f32x2 %0, %1, %2, %0;" : "+l"(d) : "l"(a), "l"(b));
}
__device__ __forceinline__ float2 unp2(u64 v) {
    float lo, hi; asm("mov.b64 {%0, %1}, %2;" : "=f"(lo), "=f"(hi) : "l"(v));
    return make_float2(lo, hi);
}

// Scratch: 6 spatial channels + 8 per-image constants
__device__ float g_inp6[(size_t)BTOT * 6 * HW];
__device__ float g_cst[(size_t)BTOT * 8];

// ---------------------------------------------------------------------------
// Kernel 1: per-image statistics
// ---------------------------------------------------------------------------
__global__ __launch_bounds__(256) void stats_kernel(
    const float* __restrict__ ts,
    const float* __restrict__ ptm,
    const float* __restrict__ pmt,
    const float* __restrict__ piou,
    const void* __restrict__ mask_raw)
{
    const int b = blockIdx.x;
    const int tid = threadIdx.x;
    const int lane = tid & 31;
    const int wid = tid >> 5;

    __shared__ float mf[NMEM], ow[NMEM];
    __shared__ float pmax[NMEM];
    __shared__ float warpmax[8];
    __shared__ float sc[16]; // 0:max_ts 1..6:m_mm,s_mm,m_gm,s_gm,m_om,s_om 7:ca 8:cg 9:co

    unsigned int w0 = *(const unsigned int*)mask_raw;
    int mode = (w0 == 1u) ? 1 : ((w0 == 0x3F800000u) ? 2 : 0);

    if (tid == 0) {
        float run = 0.f, ca = 0.f, cg = 0.f, co = 0.f;
        for (int m = 0; m < NMEM; ++m) {
            int idx = b * NMEM + m;
            float f;
            if (mode == 1)      f = (((const int*)mask_raw)[idx] != 0) ? 1.f : 0.f;
            else if (mode == 2) f = (((const float*)mask_raw)[idx] != 0.f) ? 1.f : 0.f;
            else                f = (((const unsigned char*)mask_raw)[idx] != 0) ? 1.f : 0.f;
            run += f;
            float rank = run - 1.f;
            float g = (rank < (float)NGTH_) ? f : 0.f;
            float o = f - g;
            mf[m] = f; ow[m] = o;
            ca += f; cg += g; co += o;
        }
        sc[7] = ca; sc[8] = cg; sc[9] = co;
    }

    float tmax = -INFINITY;
    const float* tsb = ts + (size_t)b * HW;
    for (int p = tid; p < HW; p += 256) tmax = fmaxf(tmax, tsb[p]);
    #pragma unroll
    for (int off = 16; off > 0; off >>= 1)
        tmax = fmaxf(tmax, __shfl_xor_sync(0xffffffffu, tmax, off));
    if (lane == 0) warpmax[wid] = tmax;

    const float* ptmb = ptm + (size_t)b * NMEM * HW;
    for (int m = wid; m < NMEM; m += 8) {
        float mx = -INFINITY;
        const float* pr = ptmb + (size_t)m * HW;
        for (int p = lane; p < HW; p += 32) mx = fmaxf(mx, pr[p]);
        #pragma unroll
        for (int off = 16; off > 0; off >>= 1)
            mx = fmaxf(mx, __shfl_xor_sync(0xffffffffu, mx, off));
        if (lane == 0) pmax[m] = mx;
    }
    __syncthreads();

    if (wid == 0) {
        float v = (lane < 8) ? warpmax[lane] : -INFINITY;
        #pragma unroll
        for (int off = 4; off > 0; off >>= 1)
            v = fmaxf(v, __shfl_xor_sync(0xffffffffu, v, off));
        if (lane == 0) sc[0] = v;
    }
    if (wid == 1) {
        float v  = (lane < NMEM) ? pmax[lane] : 0.f;
        float fa = (lane < NMEM) ? mf[lane] : 0.f;
        float fo = (lane < NMEM) ? ow[lane] : 0.f;
        float fg = fa - fo;
        float sa = v * fa, ssa = v * v * fa;
        float sg = v * fg, ssg = v * v * fg;
        float so = v * fo, sso = v * v * fo;
        #pragma unroll
        for (int off = 16; off > 0; off >>= 1) {
            sa  += __shfl_xor_sync(0xffffffffu, sa, off);
            ssa += __shfl_xor_sync(0xffffffffu, ssa, off);
            sg  += __shfl_xor_sync(0xffffffffu, sg, off);
            ssg += __shfl_xor_sync(0xffffffffu, ssg, off);
            so  += __shfl_xor_sync(0xffffffffu, so, off);
            sso += __shfl_xor_sync(0xffffffffu, sso, off);
        }
        if (lane == 0) {
            float ca = sc[7], cg = sc[8], co = sc[9];
            float mA = sa / ca; sc[1] = mA; sc[2] = sqrtf(fmaxf(ssa / ca - mA * mA, 0.f));
            float mG = sg / cg; sc[3] = mG; sc[4] = sqrtf(fmaxf(ssg / cg - mG * mG, 0.f));
            float mO = so / co; sc[5] = mO; sc[6] = sqrtf(fmaxf(sso / co - mO * mO, 0.f));
        }
    }
    __syncthreads();

    if (tid == 0) {
        float* c = g_cst + (size_t)b * 8;
        c[0] = sc[0]; c[1] = piou[b];
        c[2] = sc[1]; c[3] = sc[2]; c[4] = sc[3];
        c[5] = sc[4]; c[6] = sc[5]; c[7] = sc[6];
    }

    float* ob = g_inp6 + (size_t)b * 6 * HW;
    const float* pmtb = pmt + (size_t)b * NMEM * HW;
    const float ca = sc[7], co = sc[9];

    for (int p = tid; p < HW; p += 256) {
        float sa = 0, ssa = 0, sg = 0, ssg = 0, so = 0, sso = 0;
        #pragma unroll 5
        for (int m = 0; m < NMEM; ++m) {
            float v = pmtb[(size_t)m * HW + p];
            float fa = mf[m], fo = ow[m];
            sa += v * fa; ssa += v * v * fa;
            if (m < NGTH_) { sg += v; ssg += v * v; }
            so += v * fo; sso += v * v * fo;
        }
        float mA = sa / ca, sA = sqrtf(fmaxf(ssa / ca - mA * mA, 0.f));
        float mG = sg * (1.f / NGTH_), sG = sqrtf(fmaxf(ssg * (1.f / NGTH_) - mG * mG, 0.f));
        float mO = so / co, sO = sqrtf(fmaxf(sso / co - mO * mO, 0.f));
        ob[0 * HW + p] = mA;
        ob[1 * HW + p] = sA;
        ob[2 * HW + p] = mG;
        ob[3 * HW + p] = sG;
        ob[4 * HW + p] = mO;
        ob[5 * HW + p] = sO;
    }
}

// ---------------------------------------------------------------------------
// Fused CNN kernel (f32x2 packed FMA over output-channel pairs)
// smem float layout:
//   A   [0,     13312)  conv1 input (6x32x32=6144) / x2 (64x13x16=13312)
//   B   [13312, 28672)  x1 pooled (64x15x16=15360) / x3 (64x11x12=8448)
//   W   [28672, 49152)  weight halves [ocp][icl][9 taps x 2 oc] padded to 20
//   E   [49152, 49280)  folded BN scale[64]+bias[64]
//   RED [49280, 49296)
// ---------------------------------------------------------------------------
#define OA 0
#define OB 13312
#define OWT 28672
#define OE 49152
#define ORED 49280
#define SMEM_FLOATS 49328
#define SMEM_BYTES (SMEM_FLOATS * 4)

__global__ __launch_bounds__(TPB, 1) void cnn_kernel(
    const float* __restrict__ w1, const float* __restrict__ cb1,
    const float* __restrict__ g1, const float* __restrict__ bb1,
    const float* __restrict__ m1, const float* __restrict__ v1,
    const float* __restrict__ w2, const float* __restrict__ cb2,
    const float* __restrict__ g2, const float* __restrict__ bb2,
    const float* __restrict__ m2, const float* __restrict__ v2,
    const float* __restrict__ w3, const float* __restrict__ cb3,
    const float* __restrict__ g3, const float* __restrict__ bb3,
    const float* __restrict__ m3, const float* __restrict__ v3,
    const float* __restrict__ w4, const float* __restrict__ cb4,
    float* __restrict__ out)
{
    extern __shared__ float sm[];
    const int b = blockIdx.x;
    const int tid = threadIdx.x;

    // ---------------- prologue: input6, conv1 weights (pair layout), E1 ----------------
    {
        const float* src = g_inp6 + (size_t)b * 6 * HW;
        for (int i = tid; i < 6 * HW; i += TPB) sm[OA + i] = src[i];
        // conv1 weights: ic_global = c+2 (spatial channels), pair layout
        for (int i = tid; i < 64 * 6 * 9; i += TPB) {
            int oc = i / 54; int r = i - oc * 54;
            int c = r / 9; int t = r - c * 9;
            sm[OWT + ((oc >> 1) * 6 + c) * 20 + t * 2 + (oc & 1)] =
                w1[oc * 126 + (c + 2) * 9 + t];
        }
        if (tid < 64) {
            const float* cst = g_cst + (size_t)b * 8;
            float extra = 0.f;
            #pragma unroll
            for (int j = 0; j < 8; ++j) {
                int ic = (j < 2) ? j : (j + 6);
                const float* wb = w1 + tid * 126 + ic * 9;
                float s9 = 0.f;
                #pragma unroll
                for (int t = 0; t < 9; ++t) s9 += wb[t];
                extra += cst[j] * s9;
            }
            float s = g1[tid] * rsqrtf(v1[tid] + 1e-5f);
            sm[OE + tid] = s;
            sm[OE + 64 + tid] = s * (extra + cb1[tid] - m1[tid]) + bb1[tid];
        }
    }
    __syncthreads();

    // ---------------- stage 1: conv1 (6ic, 32x32->30x30) + bn + relu + 2x2 pool ----------------
    // item: 4 oc (2 pairs) x 1 pooled row x 1 pooled col; 16*15*15 = 3600 items
    for (int it = tid; it < 3600; it += TPB) {
        int pt = it % 15;
        int pr = (it / 15) % 15;
        int ocg = it / 225;
        int x0 = 2 * pt, r0 = 2 * pr;

        u64 acc[2][4];
        #pragma unroll
        for (int p = 0; p < 2; ++p)
            #pragma unroll
            for (int a = 0; a < 4; ++a) acc[p][a] = 0ull;

        for (int c = 0; c < 6; ++c) {
            const float* ib = &sm[OA + c * 1024 + r0 * 32 + x0];
            u64 d[4][4];
            #pragma unroll
            for (int rr = 0; rr < 4; ++rr) {
                float2 a0 = *(const float2*)(ib + rr * 32);
                float2 a1 = *(const float2*)(ib + rr * 32 + 2);
                d[rr][0] = dup2f(a0.x); d[rr][1] = dup2f(a0.y);
                d[rr][2] = dup2f(a1.x); d[rr][3] = dup2f(a1.y);
            }
            #pragma unroll
            for (int p = 0; p < 2; ++p) {
                const u64* wp = (const u64*)&sm[OWT + ((ocg * 2 + p) * 6 + c) * 20];
                #pragma unroll
                for (int ky = 0; ky < 3; ++ky)
                    #pragma unroll
                    for (int kx = 0; kx < 3; ++kx) {
                        u64 wv = wp[ky * 3 + kx];
                        fma2(acc[p][0], wv, d[ky][kx]);
                        fma2(acc[p][1], wv, d[ky][kx + 1]);
                        fma2(acc[p][2], wv, d[ky + 1][kx]);
                        fma2(acc[p][3], wv, d[ky + 1][kx + 1]);
                    }
            }
        }
        #pragma unroll
        for (int p = 0; p < 2; ++p) {
            int oc0 = ocg * 4 + p * 2;
            float s0 = sm[OE + oc0],     bi0 = sm[OE + 64 + oc0];
            float s1 = sm[OE + oc0 + 1], bi1 = sm[OE + 64 + oc0 + 1];
            float2 q0 = unp2(acc[p][0]), q1 = unp2(acc[p][1]);
            float2 q2 = unp2(acc[p][2]), q3 = unp2(acc[p][3]);
            float lo = fmaxf(fmaxf(fmaxf(s0 * q0.x + bi0, 0.f), fmaxf(s0 * q1.x + bi0, 0.f)),
                             fmaxf(fmaxf(s0 * q2.x + bi0, 0.f), fmaxf(s0 * q3.x + bi0, 0.f)));
            float hi = fmaxf(fmaxf(fmaxf(s1 * q0.y + bi1, 0.f), fmaxf(s1 * q1.y + bi1, 0.f)),
                             fmaxf(fmaxf(s1 * q2.y + bi1, 0.f), fmaxf(s1 * q3.y + bi1, 0.f)));
            sm[OB + oc0 * 240 + pr * 16 + pt] = lo;
            sm[OB + (oc0 + 1) * 240 + pr * 16 + pt] = hi;
        }
    }

    // ---------------- stage 2: conv2 (64->64, 15x15 -> 13x13), B -> A ----------------
    // item: 4 oc (2 pairs) x 1 row x 2 cols; 16*13*7 = 1456 items, 3 rounds
    {
        u64 acc2s[3][4];
        #pragma unroll
        for (int r = 0; r < 3; ++r)
            #pragma unroll
            for (int a = 0; a < 4; ++a) acc2s[r][a] = 0ull;

        for (int h = 0; h < 2; ++h) {
            __syncthreads();
            for (int i = tid; i < 64 * 32 * 9; i += TPB) {
                int oc = i / 288; int r = i - oc * 288;
                int icl = r / 9; int t = r - icl * 9;
                sm[OWT + ((oc >> 1) * 32 + icl) * 20 + t * 2 + (oc & 1)] =
                    w2[oc * 576 + h * 288 + r];
            }
            if (h == 0 && tid < 64) {
                float s = g2[tid] * rsqrtf(v2[tid] + 1e-5f);
                sm[OE + tid] = s;
                sm[OE + 64 + tid] = s * (cb2[tid] - m2[tid]) + bb2[tid];
            }
            __syncthreads();

            #pragma unroll
            for (int r = 0; r < 3; ++r) {
                int it = tid + r * TPB;
                if (it >= 1456) break;
                int ct = it % 7;
                int row = (it / 7) % 13;
                int ocg = it / 91;
                int x0 = 2 * ct;
                const float* ibase = &sm[OB + h * 32 * 240 + row * 16 + x0];
                for (int icl = 0; icl < 32; ++icl) {
                    const float* ib = ibase + icl * 240;
                    u64 d[3][4];
                    #pragma unroll
                    for (int rr = 0; rr < 3; ++rr) {
                        float2 a0 = *(const float2*)(ib + rr * 16);
                        float2 a1 = *(const float2*)(ib + rr * 16 + 2);
                        d[rr][0] = dup2f(a0.x); d[rr][1] = dup2f(a0.y);
                        d[rr][2] = dup2f(a1.x); d[rr][3] = dup2f(a1.y);
                    }
                    #pragma unroll
                    for (int p = 0; p < 2; ++p) {
                        const u64* wp = (const u64*)&sm[OWT + ((ocg * 2 + p) * 32 + icl) * 20];
                        #pragma unroll
                        for (int ky = 0; ky < 3; ++ky)
                            #pragma unroll
                            for (int kx = 0; kx < 3; ++kx) {
                                u64 wv = wp[ky * 3 + kx];
                                fma2(acc2s[r][p * 2 + 0], wv, d[ky][kx]);
                                fma2(acc2s[r][p * 2 + 1], wv, d[ky][kx + 1]);
                            }
                    }
                }
            }
        }
        #pragma unroll
        for (int r = 0; r < 3; ++r) {
            int it = tid + r * TPB;
            if (it >= 1456) break;
            int ct = it % 7;
            int row = (it / 7) % 13;
            int ocg = it / 91;
            int x0 = 2 * ct;
            #pragma unroll
            for (int p = 0; p < 2; ++p) {
                int oc0 = ocg * 4 + p * 2;
                float s0 = sm[OE + oc0],     bi0 = sm[OE + 64 + oc0];
                float s1 = sm[OE + oc0 + 1], bi1 = sm[OE + 64 + oc0 + 1];
                #pragma unroll
                for (int c2 = 0; c2 < 2; ++c2) {
                    int x = x0 + c2;
                    if (x < 13) {
                        float2 v = unp2(acc2s[r][p * 2 + c2]);
                        sm[OA + oc0 * 208 + row * 16 + x] = fmaxf(s0 * v.x + bi0, 0.f);
                        sm[OA + (oc0 + 1) * 208 + row * 16 + x] = fmaxf(s1 * v.y + bi1, 0.f);
                    }
                }
            }
        }
    }

    // ---------------- stage 3: conv3 (64->64, 13x13 -> 11x11), A -> B ----------------
    // item: 8 oc (4 pairs) x 1 position; 8*121 = 968 items, 2 rounds
    {
        u64 acc3s[2][4];
        #pragma unroll
        for (int r = 0; r < 2; ++r)
            #pragma unroll
            for (int a = 0; a < 4; ++a) acc3s[r][a] = 0ull;

        for (int h = 0; h < 2; ++h) {
            __syncthreads();
            for (int i = tid; i < 64 * 32 * 9; i += TPB) {
                int oc = i / 288; int r = i - oc * 288;
                int icl = r / 9; int t = r - icl * 9;
                sm[OWT + ((oc >> 1) * 32 + icl) * 20 + t * 2 + (oc & 1)] =
                    w3[oc * 576 + h * 288 + r];
            }
            if (h == 0 && tid < 64) {
                float s = g3[tid] * rsqrtf(v3[tid] + 1e-5f);
                sm[OE + tid] = s;
                sm[OE + 64 + tid] = s * (cb3[tid] - m3[tid]) + bb3[tid];
            }
            __syncthreads();

            #pragma unroll
            for (int r = 0; r < 2; ++r) {
                int it = tid + r * TPB;
                if (it >= 968) break;
                int pos = it % 121;
                int ocg = it / 121;
                int y = pos / 11, x = pos - y * 11;
                const float* ibase = &sm[OA + h * 32 * 208 + y * 16 + x];
                for (int icl = 0; icl < 32; ++icl) {
                    const float* ib = ibase + icl * 208;
                    u64 d[9];
                    #pragma unroll
                    for (int rr = 0; rr < 3; ++rr)
                        #pragma unroll
                        for (int k = 0; k < 3; ++k)
                            d[rr * 3 + k] = dup2f(ib[rr * 16 + k]);
                    #pragma unroll
                    for (int p = 0; p < 4; ++p) {
                        const u64* wp = (const u64*)&sm[OWT + ((ocg * 4 + p) * 32 + icl) * 20];
                        #pragma unroll
                        for (int t = 0; t < 9; ++t)
                            fma2(acc3s[r][p], wp[t], d[t]);
                    }
                }
            }
        }
        #pragma unroll
        for (int r = 0; r < 2; ++r) {
            int it = tid + r * TPB;
            if (it >= 968) break;
            int pos = it % 121;
            int ocg = it / 121;
            int y = pos / 11, x = pos - y * 11;
            #pragma unroll
            for (int p = 0; p < 4; ++p) {
                int oc0 = ocg * 8 + p * 2;
                float s0 = sm[OE + oc0],     bi0 = sm[OE + 64 + oc0];
                float s1 = sm[OE + oc0 + 1], bi1 = sm[OE + 64 + oc0 + 1];
                float2 v = unp2(acc3s[r][p]);
                sm[OB + oc0 * 132 + y * 12 + x] = fmaxf(s0 * v.x + bi0, 0.f);
                sm[OB + (oc0 + 1) * 132 + y * 12 + x] = fmaxf(s1 * v.y + bi1, 0.f);
            }
        }
    }

    // ---------------- stage 4: conv4 (64->1, 11x11 -> 9x9) + global max ----------------
    __syncthreads();
    for (int i = tid; i < 576; i += TPB) sm[OWT + i] = w4[i];
    __syncthreads();

    float lmax = -INFINITY;
    if (tid < 81) {
        int y = tid / 9, x = tid - (tid / 9) * 9;
        float a = 0.f;
        for (int ic = 0; ic < 64; ++ic) {
            const float* ib = &sm[OB + ic * 132 + y * 12 + x];
            const float* wb = &sm[OWT + ic * 9];
            #pragma unroll
            for (int ky = 0; ky < 3; ++ky)
                #pragma unroll
                for (int kx = 0; kx < 3; ++kx)
                    a += ib[ky * 12 + kx] * wb[ky * 3 + kx];
        }
        lmax = a;
    }
    #pragma unroll
    for (int off = 16; off > 0; off >>= 1)
        lmax = fmaxf(lmax, __shfl_xor_sync(0xffffffffu, lmax, off));
    if ((tid & 31) == 0) sm[ORED + (tid >> 5)] = lmax;
    __syncthreads();
    if (tid < 32) {
        float v = (tid < TPB / 32) ? sm[ORED + tid] : -INFINITY;
        #pragma unroll
        for (int off = 16; off > 0; off >>= 1)
            v = fmaxf(v, __shfl_xor_sync(0xffffffffu, v, off));
        if (tid == 0) out[b] = v + cb4[0];
    }
}

// ---------------------------------------------------------------------------
extern "C" void kernel_launch(void* const* d_in, const int* in_sizes, int n_in,
                              void* d_out, int out_size)
{
    cudaFuncSetAttribute(cnn_kernel, cudaFuncAttributeMaxDynamicSharedMemorySize, SMEM_BYTES);

    stats_kernel<<<BTOT, 256>>>(
        (const float*)d_in[0],   // target_scores
        (const float*)d_in[1],   // ptm
        (const float*)d_in[2],   // pmt
        (const float*)d_in[3],   // predicted_iou
        d_in[4]);                // mem_mask (dtype auto-detected)

    cnn_kernel<<<BTOT, TPB, SMEM_BYTES>>>(
        (const float*)d_in[5],  (const float*)d_in[6],
        (const float*)d_in[7],  (const float*)d_in[8],
        (const float*)d_in[9],  (const float*)d_in[10],
        (const float*)d_in[11], (const float*)d_in[12],
        (const float*)d_in[13], (const float*)d_in[14],
        (const float*)d_in[15], (const float*)d_in[16],
        (const float*)d_in[17], (const float*)d_in[18],
        (const float*)d_in[19], (const float*)d_in[20],
        (const float*)d_in[21], (const float*)d_in[22],
        (const float*)d_in[23], (const float*)d_in[24],
        (float*)d_out);
}

// round 3
// speedup vs baseline: 1.4264x; 1.3350x over previous
#include <cuda_runtime.h>
#include <math.h>

#define BTOT 512
#define NMEM 30
#define HW 1024
#define NGTH_ 15
#define TPB 480

typedef unsigned long long u64;

__device__ __forceinline__ u64 dup2f(float v) {
    u64 r; asm("mov.b64 %0, {%1, %1};" : "=l"(r) : "f"(v)); return r;
}
__device__ __forceinline__ void fma2(u64& d, u64 a, u64 b) {
    asm("fma.rn.f32x2 %0, %1, %2, %0;" : "+l"(d) : "l"(a), "l"(b));
}
__device__ __forceinline__ float2 unp2(u64 v) {
    float lo, hi; asm("mov.b64 {%0, %1}, %2;" : "=f"(lo), "=f"(hi) : "l"(v));
    return make_float2(lo, hi);
}

__device__ float g_inp6[(size_t)BTOT * 6 * HW];
__device__ float g_cst[(size_t)BTOT * 8];

// ---------------------------------------------------------------------------
// Kernel 1: per-image statistics
// ---------------------------------------------------------------------------
__global__ __launch_bounds__(256) void stats_kernel(
    const float* __restrict__ ts,
    const float* __restrict__ ptm,
    const float* __restrict__ pmt,
    const float* __restrict__ piou,
    const void* __restrict__ mask_raw)
{
    const int b = blockIdx.x;
    const int tid = threadIdx.x;
    const int lane = tid & 31;
    const int wid = tid >> 5;

    __shared__ float mf[NMEM], ow[NMEM];
    __shared__ float pmax[NMEM];
    __shared__ float warpmax[8];
    __shared__ float sc[16];

    unsigned int w0 = *(const unsigned int*)mask_raw;
    int mode = (w0 == 1u) ? 1 : ((w0 == 0x3F800000u) ? 2 : 0);

    if (tid == 0) {
        float run = 0.f, ca = 0.f, cg = 0.f, co = 0.f;
        for (int m = 0; m < NMEM; ++m) {
            int idx = b * NMEM + m;
            float f;
            if (mode == 1)      f = (((const int*)mask_raw)[idx] != 0) ? 1.f : 0.f;
            else if (mode == 2) f = (((const float*)mask_raw)[idx] != 0.f) ? 1.f : 0.f;
            else                f = (((const unsigned char*)mask_raw)[idx] != 0) ? 1.f : 0.f;
            run += f;
            float rank = run - 1.f;
            float g = (rank < (float)NGTH_) ? f : 0.f;
            float o = f - g;
            mf[m] = f; ow[m] = o;
            ca += f; cg += g; co += o;
        }
        sc[7] = ca; sc[8] = cg; sc[9] = co;
    }

    float tmax = -INFINITY;
    const float* tsb = ts + (size_t)b * HW;
    for (int p = tid; p < HW; p += 256) tmax = fmaxf(tmax, tsb[p]);
    #pragma unroll
    for (int off = 16; off > 0; off >>= 1)
        tmax = fmaxf(tmax, __shfl_xor_sync(0xffffffffu, tmax, off));
    if (lane == 0) warpmax[wid] = tmax;

    const float* ptmb = ptm + (size_t)b * NMEM * HW;
    for (int m = wid; m < NMEM; m += 8) {
        float mx = -INFINITY;
        const float* pr = ptmb + (size_t)m * HW;
        for (int p = lane; p < HW; p += 32) mx = fmaxf(mx, pr[p]);
        #pragma unroll
        for (int off = 16; off > 0; off >>= 1)
            mx = fmaxf(mx, __shfl_xor_sync(0xffffffffu, mx, off));
        if (lane == 0) pmax[m] = mx;
    }
    __syncthreads();

    if (wid == 0) {
        float v = (lane < 8) ? warpmax[lane] : -INFINITY;
        #pragma unroll
        for (int off = 4; off > 0; off >>= 1)
            v = fmaxf(v, __shfl_xor_sync(0xffffffffu, v, off));
        if (lane == 0) sc[0] = v;
    }
    if (wid == 1) {
        float v  = (lane < NMEM) ? pmax[lane] : 0.f;
        float fa = (lane < NMEM) ? mf[lane] : 0.f;
        float fo = (lane < NMEM) ? ow[lane] : 0.f;
        float fg = fa - fo;
        float sa = v * fa, ssa = v * v * fa;
        float sg = v * fg, ssg = v * v * fg;
        float so = v * fo, sso = v * v * fo;
        #pragma unroll
        for (int off = 16; off > 0; off >>= 1) {
            sa  += __shfl_xor_sync(0xffffffffu, sa, off);
            ssa += __shfl_xor_sync(0xffffffffu, ssa, off);
            sg  += __shfl_xor_sync(0xffffffffu, sg, off);
            ssg += __shfl_xor_sync(0xffffffffu, ssg, off);
            so  += __shfl_xor_sync(0xffffffffu, so, off);
            sso += __shfl_xor_sync(0xffffffffu, sso, off);
        }
        if (lane == 0) {
            float ca = sc[7], cg = sc[8], co = sc[9];
            float mA = sa / ca; sc[1] = mA; sc[2] = sqrtf(fmaxf(ssa / ca - mA * mA, 0.f));
            float mG = sg / cg; sc[3] = mG; sc[4] = sqrtf(fmaxf(ssg / cg - mG * mG, 0.f));
            float mO = so / co; sc[5] = mO; sc[6] = sqrtf(fmaxf(sso / co - mO * mO, 0.f));
        }
    }
    __syncthreads();

    if (tid == 0) {
        float* c = g_cst + (size_t)b * 8;
        c[0] = sc[0]; c[1] = piou[b];
        c[2] = sc[1]; c[3] = sc[2]; c[4] = sc[3];
        c[5] = sc[4]; c[6] = sc[5]; c[7] = sc[6];
    }

    float* ob = g_inp6 + (size_t)b * 6 * HW;
    const float* pmtb = pmt + (size_t)b * NMEM * HW;
    const float ca = sc[7], co = sc[9];

    for (int p = tid; p < HW; p += 256) {
        float sa = 0, ssa = 0, sg = 0, ssg = 0, so = 0, sso = 0;
        #pragma unroll 5
        for (int m = 0; m < NMEM; ++m) {
            float v = pmtb[(size_t)m * HW + p];
            float fa = mf[m], fo = ow[m];
            sa += v * fa; ssa += v * v * fa;
            if (m < NGTH_) { sg += v; ssg += v * v; }
            so += v * fo; sso += v * v * fo;
        }
        float mA = sa / ca, sA = sqrtf(fmaxf(ssa / ca - mA * mA, 0.f));
        float mG = sg * (1.f / NGTH_), sG = sqrtf(fmaxf(ssg * (1.f / NGTH_) - mG * mG, 0.f));
        float mO = so / co, sO = sqrtf(fmaxf(sso / co - mO * mO, 0.f));
        ob[0 * HW + p] = mA;
        ob[1 * HW + p] = sA;
        ob[2 * HW + p] = mG;
        ob[3 * HW + p] = sG;
        ob[4 * HW + p] = mO;
        ob[5 * HW + p] = sO;
    }
}

// ---------------------------------------------------------------------------
// Fused CNN. Conflict-free strides: tiles 18 floats/row, conv1 input 34.
// smem float layout:
//   OA  [0,     14976)  conv1 input 6x32x34=6528 / x2 64x13x18=14976
//   OB  [14976, 32256)  x1 64x15x18=17280        / x3 64x11x18=12672
//   OWT [32256, 50688)  weights (max: 32ocp x 32ic x 18 = 18432)
//   OE  [50688, 50816)  folded BN scale[64]+bias[64]
//   ORED[50816, 50832)
// ---------------------------------------------------------------------------
#define OA 0
#define OB 14976
#define OWT 32256
#define OE 50688
#define ORED 50816
#define SMEM_FLOATS 50832
#define SMEM_BYTES (SMEM_FLOATS * 4)
#define S_T 18

// 64->64 3x3 conv stage. item = 4oc x 1 row x 8 cols, ocg-major for broadcast.
template<int INCS, int OUTCS, int NR, int NC>
__device__ __forceinline__ void conv64_stage(
    float* sm, int inOff, int outOff,
    const float* __restrict__ wsrc,
    const float* __restrict__ cbv, const float* __restrict__ gv,
    const float* __restrict__ bbv, const float* __restrict__ mv,
    const float* __restrict__ vv)
{
    const int tid = threadIdx.x;
    const int NITEMS = 16 * NR * 2;
    const bool act = tid < NITEMS;
    int ocg = 0, row = 0, x0 = 0;
    if (act) {
        ocg = tid / (NR * 2);
        int r = tid - ocg * (NR * 2);
        row = r >> 1;
        x0 = (r & 1) * 8;
    }

    u64 acc[2][8];
    #pragma unroll
    for (int p = 0; p < 2; ++p)
        #pragma unroll
        for (int c = 0; c < 8; ++c) acc[p][c] = 0ull;

    for (int h = 0; h < 2; ++h) {
        __syncthreads();
        for (int i = tid; i < 64 * 32 * 9; i += TPB) {
            int oc = i / 288; int r = i - oc * 288;
            int icl = r / 9; int t = r - icl * 9;
            sm[OWT + ((oc >> 1) * 32 + icl) * 18 + t * 2 + (oc & 1)] =
                wsrc[oc * 576 + h * 288 + r];
        }
        if (h == 0 && tid < 64) {
            float s = gv[tid] * rsqrtf(vv[tid] + 1e-5f);
            sm[OE + tid] = s;
            sm[OE + 64 + tid] = s * (cbv[tid] - mv[tid]) + bbv[tid];
        }
        __syncthreads();

        if (act) {
            const float* ibase = &sm[inOff + h * 32 * INCS + row * S_T + x0];
            for (int icl = 0; icl < 32; ++icl) {
                const float* ib = ibase + icl * INCS;
                const u64* wb = (const u64*)&sm[OWT + ((ocg * 2) * 32 + icl) * 18];
                const u64* wb2 = (const u64*)&sm[OWT + ((ocg * 2 + 1) * 32 + icl) * 18];
                #pragma unroll
                for (int ky = 0; ky < 3; ++ky) {
                    u64 d[10];
                    #pragma unroll
                    for (int q = 0; q < 5; ++q) {
                        float2 a = *(const float2*)(ib + ky * S_T + 2 * q);
                        d[2 * q] = dup2f(a.x); d[2 * q + 1] = dup2f(a.y);
                    }
                    #pragma unroll
                    for (int kx = 0; kx < 3; ++kx) {
                        u64 w0 = wb[ky * 3 + kx];
                        u64 w1 = wb2[ky * 3 + kx];
                        #pragma unroll
                        for (int c = 0; c < 8; ++c) {
                            fma2(acc[0][c], w0, d[c + kx]);
                            fma2(acc[1][c], w1, d[c + kx]);
                        }
                    }
                }
            }
        }
    }

    if (act) {
        #pragma unroll
        for (int p = 0; p < 2; ++p) {
            int oc0 = ocg * 4 + 2 * p;
            float s0 = sm[OE + oc0],     bi0 = sm[OE + 64 + oc0];
            float s1 = sm[OE + oc0 + 1], bi1 = sm[OE + 64 + oc0 + 1];
            #pragma unroll
            for (int c = 0; c < 8; ++c) {
                int x = x0 + c;
                if (x < NC) {
                    float2 v = unp2(acc[p][c]);
                    sm[outOff + oc0 * OUTCS + row * S_T + x] = fmaxf(s0 * v.x + bi0, 0.f);
                    sm[outOff + (oc0 + 1) * OUTCS + row * S_T + x] = fmaxf(s1 * v.y + bi1, 0.f);
                }
            }
        }
    }
}

__global__ __launch_bounds__(TPB, 1) void cnn_kernel(
    const float* __restrict__ w1, const float* __restrict__ cb1,
    const float* __restrict__ g1, const float* __restrict__ bb1,
    const float* __restrict__ m1, const float* __restrict__ v1,
    const float* __restrict__ w2, const float* __restrict__ cb2,
    const float* __restrict__ g2, const float* __restrict__ bb2,
    const float* __restrict__ m2, const float* __restrict__ v2,
    const float* __restrict__ w3, const float* __restrict__ cb3,
    const float* __restrict__ g3, const float* __restrict__ bb3,
    const float* __restrict__ m3, const float* __restrict__ v3,
    const float* __restrict__ w4, const float* __restrict__ cb4,
    float* __restrict__ out)
{
    extern __shared__ float sm[];
    const int b = blockIdx.x;
    const int tid = threadIdx.x;

    // ---------------- prologue: input (stride 34), conv1 weights, E1 ----------------
    {
        const float* src = g_inp6 + (size_t)b * 6 * HW;
        for (int i = tid; i < 6 * HW; i += TPB) {
            int c = i >> 10; int rem = i & 1023;
            int r = rem >> 5; int x = rem & 31;
            sm[OA + c * 1088 + r * 34 + x] = src[i];
        }
        for (int i = tid; i < 64 * 6 * 9; i += TPB) {
            int oc = i / 54; int r = i - oc * 54;
            int c = r / 9; int t = r - c * 9;
            sm[OWT + ((oc >> 1) * 6 + c) * 18 + t * 2 + (oc & 1)] =
                w1[oc * 126 + (c + 2) * 9 + t];
        }
        if (tid < 64) {
            const float* cst = g_cst + (size_t)b * 8;
            float extra = 0.f;
            #pragma unroll
            for (int j = 0; j < 8; ++j) {
                int ic = (j < 2) ? j : (j + 6);
                const float* wb = w1 + tid * 126 + ic * 9;
                float s9 = 0.f;
                #pragma unroll
                for (int t = 0; t < 9; ++t) s9 += wb[t];
                extra += cst[j] * s9;
            }
            float s = g1[tid] * rsqrtf(v1[tid] + 1e-5f);
            sm[OE + tid] = s;
            sm[OE + 64 + tid] = s * (extra + cb1[tid] - m1[tid]) + bb1[tid];
        }
    }
    __syncthreads();

    // ---------------- stage 1: conv1 (6ic) + bn + relu + 2x2 pool -> x1 (OB) ----------------
    // item = 4oc x 1 pooled row x 4 pooled cols (8 conv cols x 2 conv rows); 960 items
    #pragma unroll
    for (int itb = 0; itb < 2; ++itb) {
        int it = tid + itb * TPB;
        int ocg = it / 60;
        int r = it - ocg * 60;
        int pr = r >> 2;
        int pq = r & 3;
        int x0 = 8 * pq, r0 = 2 * pr;

        u64 acc[2][2][8];
        #pragma unroll
        for (int p = 0; p < 2; ++p)
            #pragma unroll
            for (int e = 0; e < 2; ++e)
                #pragma unroll
                for (int c = 0; c < 8; ++c) acc[p][e][c] = 0ull;

        for (int ch = 0; ch < 6; ++ch) {
            const float* ib = &sm[OA + ch * 1088 + r0 * 34 + x0];
            const u64* wb0 = (const u64*)&sm[OWT + ((ocg * 2) * 6 + ch) * 18];
            const u64* wb1 = (const u64*)&sm[OWT + ((ocg * 2 + 1) * 6 + ch) * 18];
            #pragma unroll
            for (int ir = 0; ir < 4; ++ir) {
                u64 d[10];
                #pragma unroll
                for (int q = 0; q < 5; ++q) {
                    float2 a = *(const float2*)(ib + ir * 34 + 2 * q);
                    d[2 * q] = dup2f(a.x); d[2 * q + 1] = dup2f(a.y);
                }
                #pragma unroll
                for (int kx = 0; kx < 3; ++kx) {
                    if (ir <= 2) {
                        u64 wa = wb0[ir * 3 + kx], wc = wb1[ir * 3 + kx];
                        #pragma unroll
                        for (int c = 0; c < 8; ++c) {
                            fma2(acc[0][0][c], wa, d[c + kx]);
                            fma2(acc[1][0][c], wc, d[c + kx]);
                        }
                    }
                    if (ir >= 1) {
                        u64 wa = wb0[(ir - 1) * 3 + kx], wc = wb1[(ir - 1) * 3 + kx];
                        #pragma unroll
                        for (int c = 0; c < 8; ++c) {
                            fma2(acc[0][1][c], wa, d[c + kx]);
                            fma2(acc[1][1][c], wc, d[c + kx]);
                        }
                    }
                }
            }
        }
        #pragma unroll
        for (int p = 0; p < 2; ++p) {
            int oc0 = ocg * 4 + 2 * p;
            float s0 = sm[OE + oc0],     bi0 = sm[OE + 64 + oc0];
            float s1 = sm[OE + oc0 + 1], bi1 = sm[OE + 64 + oc0 + 1];
            #pragma unroll
            for (int j = 0; j < 4; ++j) {
                int pt = 4 * pq + j;
                if (pt < 15) {
                    float2 a = unp2(acc[p][0][2 * j]);
                    float2 bq = unp2(acc[p][0][2 * j + 1]);
                    float2 cq = unp2(acc[p][1][2 * j]);
                    float2 e = unp2(acc[p][1][2 * j + 1]);
                    float lo = fmaxf(fmaxf(fmaxf(s0 * a.x + bi0, 0.f), fmaxf(s0 * bq.x + bi0, 0.f)),
                                     fmaxf(fmaxf(s0 * cq.x + bi0, 0.f), fmaxf(s0 * e.x + bi0, 0.f)));
                    float hi = fmaxf(fmaxf(fmaxf(s1 * a.y + bi1, 0.f), fmaxf(s1 * bq.y + bi1, 0.f)),
                                     fmaxf(fmaxf(s1 * cq.y + bi1, 0.f), fmaxf(s1 * e.y + bi1, 0.f)));
                    sm[OB + oc0 * 270 + pr * S_T + pt] = lo;
                    sm[OB + (oc0 + 1) * 270 + pr * S_T + pt] = hi;
                }
            }
        }
    }

    // ---------------- stage 2: conv2 (15x15 -> 13x13), OB -> OA ----------------
    conv64_stage<270, 234, 13, 13>(sm, OB, OA, w2, cb2, g2, bb2, m2, v2);

    // ---------------- stage 3: conv3 (13x13 -> 11x11), OA -> OB ----------------
    conv64_stage<234, 198, 11, 11>(sm, OA, OB, w3, cb3, g3, bb3, m3, v3);

    // ---------------- stage 4: conv4 (64->1, 11x11 -> 9x9) + global max ----------------
    __syncthreads();
    for (int i = tid; i < 576; i += TPB) sm[OWT + i] = w4[i];
    __syncthreads();

    float lmax = -INFINITY;
    if (tid < 81) {
        int y = tid / 9, x = tid - (tid / 9) * 9;
        float a = 0.f;
        for (int ic = 0; ic < 64; ++ic) {
            const float* ib = &sm[OB + ic * 198 + y * S_T + x];
            const float* wb = &sm[OWT + ic * 9];
            #pragma unroll
            for (int ky = 0; ky < 3; ++ky)
                #pragma unroll
                for (int kx = 0; kx < 3; ++kx)
                    a += ib[ky * S_T + kx] * wb[ky * 3 + kx];
        }
        lmax = a;
    }
    #pragma unroll
    for (int off = 16; off > 0; off >>= 1)
        lmax = fmaxf(lmax, __shfl_xor_sync(0xffffffffu, lmax, off));
    if ((tid & 31) == 0) sm[ORED + (tid >> 5)] = lmax;
    __syncthreads();
    if (tid < 32) {
        float v = (tid < TPB / 32) ? sm[ORED + tid] : -INFINITY;
        #pragma unroll
        for (int off = 16; off > 0; off >>= 1)
            v = fmaxf(v, __shfl_xor_sync(0xffffffffu, v, off));
        if (tid == 0) out[b] = v + cb4[0];
    }
}

// ---------------------------------------------------------------------------
extern "C" void kernel_launch(void* const* d_in, const int* in_sizes, int n_in,
                              void* d_out, int out_size)
{
    cudaFuncSetAttribute(cnn_kernel, cudaFuncAttributeMaxDynamicSharedMemorySize, SMEM_BYTES);

    stats_kernel<<<BTOT, 256>>>(
        (const float*)d_in[0],   // target_scores
        (const float*)d_in[1],   // ptm
        (const float*)d_in[2],   // pmt
        (const float*)d_in[3],   // predicted_iou
        d_in[4]);                // mem_mask (dtype auto-detected)

    cnn_kernel<<<BTOT, TPB, SMEM_BYTES>>>(
        (const float*)d_in[5],  (const float*)d_in[6],
        (const float*)d_in[7],  (const float*)d_in[8],
        (const float*)d_in[9],  (const float*)d_in[10],
        (const float*)d_in[11], (const float*)d_in[12],
        (const float*)d_in[13], (const float*)d_in[14],
        (const float*)d_in[15], (const float*)d_in[16],
        (const float*)d_in[17], (const float*)d_in[18],
        (const float*)d_in[19], (const float*)d_in[20],
        (const float*)d_in[21], (const float*)d_in[22],
        (const float*)d_in[23], (const float*)d_in[24],
        (float*)d_out);
}